// round 7
// baseline (speedup 1.0000x reference)
#include <cuda_runtime.h>
#include <cuda_bf16.h>
#include <cuda_fp8.h>
#include <cstdint>

#define HD 4096
#define TT 8192

// ----------------------------------------------------------------------------
// Scratch (static device globals — no allocation anywhere)
// ----------------------------------------------------------------------------
__device__ float          g_resid[(size_t)TT * HD];          // 128 MB
__device__ __nv_bfloat16  g_Abuf[(size_t)TT * HD];           // 64 MB
__device__ __nv_bfloat16  g_Bbuf[3ull * HD * HD];            // 96 MB

// ----------------------------------------------------------------------------
// FP4 / FP8 emulation matching the reference semantics
// ----------------------------------------------------------------------------
// e2m1 round-to-nearest with ties-up (== jnp.searchsorted(mids, a, 'right')).
// For a >= 1: add half-ulp of the 1-mantissa-bit grid and truncate.
// Verified: 1.25->1.5, 2.5->3, 3.5->4, 5->6 (ties up); 4.9->4; 6->6.
__device__ __forceinline__ float fp4_round_dev(float x) {
    float a = fabsf(x);
    float v;
    if (a >= 1.0f) {
        a = fminf(a, 6.0f);
        uint32_t u = __float_as_uint(a);
        u = (u + 0x00200000u) & 0xFFC00000u;
        v = __uint_as_float(u);
    } else {
        v = (a < 0.25f) ? 0.0f : ((a < 0.75f) ? 0.5f : 1.0f);
    }
    return copysignf(v, x);
}

__device__ __forceinline__ float fp8_e4m3_round(float s) {
    __nv_fp8_storage_t st = __nv_cvt_float_to_fp8(s, __NV_SATFINITE, __NV_E4M3);
    return __half2float(__nv_cvt_fp8_to_halfraw(st, __NV_E4M3));
}

// Quantize one 16-element block -> dequantized bf16 (exact: <=6 sig bits)
__device__ __forceinline__ void quant16(const float y[16], float gs, unsigned short o[16]) {
    float amax = 0.0f;
#pragma unroll
    for (int j = 0; j < 16; j++) amax = fmaxf(amax, fabsf(y[j]));
    float sc = fminf((amax / 6.0f) * gs, 448.0f);
    sc = fp8_e4m3_round(sc);
    float safe = (sc > 0.0f) ? sc : 1.0f;
    float mult = gs / safe;
#pragma unroll
    for (int j = 0; j < 16; j++) {
        float q = fp4_round_dev(y[j] * mult);
        o[j] = __bfloat16_as_ushort(__float2bfloat16(q * sc));
    }
}

// ----------------------------------------------------------------------------
// Weight quantize-dequantize: w rows [row0, row0+nrows) -> bf16
// ----------------------------------------------------------------------------
__global__ void __launch_bounds__(256) quantw_kernel(const float* __restrict__ w,
                                                     const float* __restrict__ wg,
                                                     __nv_bfloat16* __restrict__ bout,
                                                     int row0) {
    const int r = blockIdx.x + row0;     // global row 0 .. 3*HD-1
    const int tid = threadIdx.x;
    const float gs = wg[r >> 12];
    const float* rp = w + (size_t)r * HD + tid * 16;
    float y[16];
#pragma unroll
    for (int k = 0; k < 4; k++) {
        float4 x = *(const float4*)(rp + k * 4);
        y[k*4+0] = x.x; y[k*4+1] = x.y; y[k*4+2] = x.z; y[k*4+3] = x.w;
    }
    unsigned short o16[16];
    quant16(y, gs, o16);
    uint32_t pk[8];
#pragma unroll
    for (int k = 0; k < 8; k++) pk[k] = (uint32_t)o16[2*k] | ((uint32_t)o16[2*k+1] << 16);
    uint4* dst = (uint4*)(bout + (size_t)r * HD + tid * 16);
    dst[0] = make_uint4(pk[0], pk[1], pk[2], pk[3]);
    dst[1] = make_uint4(pk[4], pk[5], pk[6], pk[7]);
}

// ----------------------------------------------------------------------------
// Fused (optional relu) + rmsnorm + (quantize to bf16 A  |  fp32 y out)
// ----------------------------------------------------------------------------
__global__ void __launch_bounds__(256) norm_quant_kernel(
    const float* __restrict__ in, float* __restrict__ resid_out,
    const float* __restrict__ nw, const float* __restrict__ gsp,
    __nv_bfloat16* __restrict__ aout, float* __restrict__ yout, int do_relu) {
    __shared__ float red[8];
    __shared__ float s_r;
    const int t = blockIdx.x;
    const int tid = threadIdx.x;
    const int wid = tid >> 5, lid = tid & 31;

    const float* rowp = in + (size_t)t * HD + tid * 16;
    float v[16];
#pragma unroll
    for (int k = 0; k < 4; k++) {
        float4 x = *(const float4*)(rowp + k * 4);
        v[k*4+0] = x.x; v[k*4+1] = x.y; v[k*4+2] = x.z; v[k*4+3] = x.w;
    }
    if (do_relu) {
#pragma unroll
        for (int j = 0; j < 16; j++) v[j] = fmaxf(v[j], 0.0f);
        float* rp = resid_out + (size_t)t * HD + tid * 16;
#pragma unroll
        for (int k = 0; k < 4; k++)
            *(float4*)(rp + k * 4) = make_float4(v[k*4+0], v[k*4+1], v[k*4+2], v[k*4+3]);
    }
    float ss = 0.0f;
#pragma unroll
    for (int j = 0; j < 16; j++) ss += v[j] * v[j];
#pragma unroll
    for (int o = 16; o > 0; o >>= 1) ss += __shfl_xor_sync(0xffffffffu, ss, o);
    if (lid == 0) red[wid] = ss;
    __syncthreads();
    if (tid == 0) {
        float s = red[0]+red[1]+red[2]+red[3]+red[4]+red[5]+red[6]+red[7];
        s_r = rsqrtf(s * (1.0f / (float)HD) + 1e-6f);
    }
    __syncthreads();
    const float r = s_r;

    const float* wp = nw + tid * 16;
    float y[16];
#pragma unroll
    for (int k = 0; k < 4; k++) {
        float4 wv = *(const float4*)(wp + k * 4);
        y[k*4+0] = (v[k*4+0] * r) * wv.x;
        y[k*4+1] = (v[k*4+1] * r) * wv.y;
        y[k*4+2] = (v[k*4+2] * r) * wv.z;
        y[k*4+3] = (v[k*4+3] * r) * wv.w;
    }
    if (yout) {
        float* op = yout + (size_t)t * HD + tid * 16;
#pragma unroll
        for (int k = 0; k < 4; k++)
            *(float4*)(op + k * 4) = make_float4(y[k*4+0], y[k*4+1], y[k*4+2], y[k*4+3]);
    } else {
        unsigned short o16[16];
        quant16(y, gsp[0], o16);
        uint32_t pk[8];
#pragma unroll
        for (int k = 0; k < 8; k++) pk[k] = (uint32_t)o16[2*k] | ((uint32_t)o16[2*k+1] << 16);
        uint4* dst = (uint4*)(aout + (size_t)t * HD + tid * 16);
        dst[0] = make_uint4(pk[0], pk[1], pk[2], pk[3]);
        dst[1] = make_uint4(pk[4], pk[5], pk[6], pk[7]);
    }
}

// ----------------------------------------------------------------------------
// HMMA GEMM: resid[m,n] += (sum_k A[m,k]*B[n,k]) * alpha
// CTA tile 256x128, BK=64, SW128 smem, 4-stage cp.async pipeline (prefetch 3).
// 512 threads = 16 warps in a 4(M) x 4(N) grid; warp tile 64x32.
// ----------------------------------------------------------------------------
#define BM 256
#define BN 128
#define BK 64
#define A_BYTES  (BM * 128)              // 32 KB per stage
#define B_BYTES  (BN * 128)              // 16 KB per stage
#define STAGE_BYTES (A_BYTES + B_BYTES)  // 48 KB
#define NSTAGE 4
#define GEMM_SMEM (NSTAGE * STAGE_BYTES) // 192 KB

__device__ __forceinline__ uint32_t sw128(uint32_t off) {
    return off ^ ((off >> 3) & 0x70u);
}

__device__ __forceinline__ void cp16(uint32_t saddr, const void* gaddr) {
    asm volatile("cp.async.cg.shared.global [%0], [%1], 16;" :: "r"(saddr), "l"(gaddr));
}

__device__ __forceinline__ void ldm_x4(uint32_t* r, uint32_t addr) {
    asm volatile("ldmatrix.sync.aligned.m8n8.x4.shared.b16 {%0,%1,%2,%3}, [%4];"
                 : "=r"(r[0]), "=r"(r[1]), "=r"(r[2]), "=r"(r[3]) : "r"(addr));
}

__device__ __forceinline__ void mma16816(float* c, const uint32_t* a, const uint32_t* b) {
    asm volatile(
        "mma.sync.aligned.m16n8k16.row.col.f32.bf16.bf16.f32 "
        "{%0,%1,%2,%3}, {%4,%5,%6,%7}, {%8,%9}, {%0,%1,%2,%3};"
        : "+f"(c[0]), "+f"(c[1]), "+f"(c[2]), "+f"(c[3])
        : "r"(a[0]), "r"(a[1]), "r"(a[2]), "r"(a[3]), "r"(b[0]), "r"(b[1]));
}

__global__ void __launch_bounds__(512, 1) gemm_kernel(
    const __nv_bfloat16* __restrict__ A, const __nv_bfloat16* __restrict__ B,
    const float* __restrict__ agp, const float* __restrict__ wgp,
    float* __restrict__ resid) {
    extern __shared__ char smem[];
    const uint32_t sb = (uint32_t)__cvta_generic_to_shared(smem);
    const int tid = threadIdx.x;
    const int wid = tid >> 5, lane = tid & 31;
    const int n0 = blockIdx.x * BN, m0 = blockIdx.y * BM;
    const int wm = (wid & 3) * 64;       // warp M offset (4 warps cover 256)
    const int wn = (wid >> 2) * 32;      // warp N offset (4 warps cover 128)

    const __nv_bfloat16* Ab = A + (size_t)m0 * HD;
    const __nv_bfloat16* Bb = B + (size_t)n0 * HD;

    // per-warp swizzled LDSM base addresses (ks = 0); ks advances by XOR ks*32
    // (no carry into bits 7..9: base bits 5..6 are zero pre-swizzle)
    uint32_t aOff[4], bOff[2];
#pragma unroll
    for (int mt = 0; mt < 4; mt++) {
        int row = wm + mt * 16 + (lane & 15);
        aOff[mt] = sw128((uint32_t)(row * 128 + ((lane >> 4) << 4)));
    }
#pragma unroll
    for (int p = 0; p < 2; p++) {
        int nrow = wn + p * 16 + ((lane >> 4) << 3) + (lane & 7);
        bOff[p] = sw128((uint32_t)(nrow * 128 + (((lane >> 3) & 1) << 4)));
    }

    float acc[4][4][4];
#pragma unroll
    for (int i = 0; i < 4; i++)
#pragma unroll
        for (int j = 0; j < 4; j++)
#pragma unroll
            for (int q = 0; q < 4; q++) acc[i][j][q] = 0.0f;

    // --- async stage loader: A 2048 + B 1024 x 16B chunks, 512 threads
    auto load_tile = [&](int buf, int c) {
        const int k0 = c * BK;
        const uint32_t abase = sb + (uint32_t)buf * STAGE_BYTES;
        const uint32_t bbase = abase + A_BYTES;
#pragma unroll
        for (int it = 0; it < 4; it++) {
            int l = tid + it * 512;              // 0..2047
            int row = l >> 3, ch = l & 7;
            cp16(abase + sw128((uint32_t)(row * 128 + ch * 16)),
                 Ab + (size_t)row * HD + k0 + ch * 8);
        }
#pragma unroll
        for (int it = 0; it < 2; it++) {
            int l = tid + it * 512;              // 0..1023
            int row = l >> 3, ch = l & 7;
            cp16(bbase + sw128((uint32_t)(row * 128 + ch * 16)),
                 Bb + (size_t)row * HD + k0 + ch * 8);
        }
        asm volatile("cp.async.commit_group;");
    };

    const int NT = HD / BK;                       // 64
    load_tile(0, 0);
    load_tile(1, 1);
    load_tile(2, 2);

    for (int c = 0; c < NT; c++) {
        if (c + 1 < NT) asm volatile("cp.async.wait_group 2;");
        else            asm volatile("cp.async.wait_group 0;");
        __syncthreads();
        if (c + 3 < NT) load_tile((c + 3) % NSTAGE, c + 3);

        const uint32_t aBase = sb + (uint32_t)(c % NSTAGE) * STAGE_BYTES;
        const uint32_t bBase = aBase + A_BYTES;
#pragma unroll
        for (int ks = 0; ks < 4; ks++) {
            const uint32_t kx = (uint32_t)(ks * 32);
            uint32_t af[4][4];
#pragma unroll
            for (int mt = 0; mt < 4; mt++)
                ldm_x4(af[mt], aBase + (aOff[mt] ^ kx));
            uint32_t bf[2][4];
#pragma unroll
            for (int p = 0; p < 2; p++)
                ldm_x4(bf[p], bBase + (bOff[p] ^ kx));
#pragma unroll
            for (int mt = 0; mt < 4; mt++)
#pragma unroll
                for (int p = 0; p < 2; p++) {
                    mma16816(acc[mt][2 * p],     af[mt], &bf[p][0]);
                    mma16816(acc[mt][2 * p + 1], af[mt], &bf[p][2]);
                }
        }
    }

    // --- epilogue: resid += acc * alpha (fragment-direct float2 RMW)
    const float alpha = 1.0f / (wgp[0] * agp[0]);
#pragma unroll
    for (int mt = 0; mt < 4; mt++) {
        int rbase = m0 + wm + mt * 16 + (lane >> 2);
#pragma unroll
        for (int nt = 0; nt < 4; nt++) {
            int col = n0 + wn + nt * 8 + (lane & 3) * 2;
            {
                float* p = resid + (size_t)rbase * HD + col;
                float2 r = *(float2*)p;
                r.x += acc[mt][nt][0] * alpha;
                r.y += acc[mt][nt][1] * alpha;
                *(float2*)p = r;
            }
            {
                float* p = resid + (size_t)(rbase + 8) * HD + col;
                float2 r = *(float2*)p;
                r.x += acc[mt][nt][2] * alpha;
                r.y += acc[mt][nt][3] * alpha;
                *(float2*)p = r;
            }
        }
    }
}

// ----------------------------------------------------------------------------
// Launch
// ----------------------------------------------------------------------------
extern "C" void kernel_launch(void* const* d_in, const int* in_sizes, int n_in,
                              void* d_out, int out_size) {
    (void)in_sizes; (void)n_in; (void)out_size;
    const float* hs = (const float*)d_in[0];
    const float* nw = (const float*)d_in[1];
    const float* w  = (const float*)d_in[2];
    const float* ag = (const float*)d_in[3];
    const float* wg = (const float*)d_in[4];
    float* out = (float*)d_out;

    void *pA = nullptr, *pB = nullptr, *pR = nullptr;
    cudaGetSymbolAddress(&pA, g_Abuf);
    cudaGetSymbolAddress(&pB, g_Bbuf);
    cudaGetSymbolAddress(&pR, g_resid);
    __nv_bfloat16* Abuf = (__nv_bfloat16*)pA;
    __nv_bfloat16* Bbuf = (__nv_bfloat16*)pB;
    float* resid = (float*)pR;

    static cudaStream_t s1 = nullptr;
    static cudaEvent_t ev_fork = nullptr, ev_join = nullptr;
    if (!s1) {
        cudaFuncSetAttribute(gemm_kernel, cudaFuncAttributeMaxDynamicSharedMemorySize,
                             GEMM_SMEM);
        cudaStreamCreateWithFlags(&s1, cudaStreamNonBlocking);
        cudaEventCreateWithFlags(&ev_fork, cudaEventDisableTiming);
        cudaEventCreateWithFlags(&ev_join, cudaEventDisableTiming);
    }

    // fork: weight quant-dequant (2 launches, off critical path) on s1,
    // concurrent with relu+rmsnorm+quant on the main stream
    cudaEventRecord(ev_fork, 0);
    cudaStreamWaitEvent(s1, ev_fork, 0);
    quantw_kernel<<<2 * HD, 256, 0, s1>>>(w, wg, Bbuf, 0);
    quantw_kernel<<<1 * HD, 256, 0, s1>>>(w, wg, Bbuf, 2 * HD);
    cudaEventRecord(ev_join, s1);

    // relu + rmsnorm(norm_w[0]) + quant(agscale[0]) ; resid = relu(hs)
    norm_quant_kernel<<<TT, 256>>>(hs, resid, nw, ag, Abuf, nullptr, 1);

    // join before GEMM 0 consumes Bbuf
    cudaStreamWaitEvent(0, ev_join, 0);

    for (int i = 0; i < 3; i++) {
        gemm_kernel<<<dim3(HD / BN, TT / BM), 512, GEMM_SMEM>>>(
            Abuf, Bbuf + (size_t)i * HD * HD, ag + i, wg + i, resid);
        if (i < 2) {
            norm_quant_kernel<<<TT, 256>>>(resid, nullptr, nw + (size_t)(i + 1) * HD,
                                           ag + (i + 1), Abuf, nullptr, 0);
        } else {
            norm_quant_kernel<<<TT, 256>>>(resid, nullptr, nw + 3ull * HD,
                                           nullptr, nullptr, out, 0);
        }
    }
}

// round 9
// speedup vs baseline: 1.0807x; 1.0807x over previous
#include <cuda_runtime.h>
#include <cuda_bf16.h>
#include <cuda_fp8.h>
#include <cstdint>

#define HD 4096
#define TT 8192

// ----------------------------------------------------------------------------
// Scratch (static device globals — no allocation anywhere)
// ----------------------------------------------------------------------------
__device__ float          g_resid[(size_t)TT * HD];          // 128 MB
__device__ __nv_bfloat16  g_Abuf[(size_t)TT * HD];           // 64 MB
__device__ __nv_bfloat16  g_Bbuf[3ull * HD * HD];            // 96 MB

// ----------------------------------------------------------------------------
// FP4 / FP8 emulation matching the reference semantics
// ----------------------------------------------------------------------------
// e2m1 round-to-nearest with ties-up (== jnp.searchsorted(mids, a, 'right')).
__device__ __forceinline__ float fp4_round_dev(float x) {
    float a = fabsf(x);
    float v;
    if (a >= 1.0f) {
        a = fminf(a, 6.0f);
        uint32_t u = __float_as_uint(a);
        u = (u + 0x00200000u) & 0xFFC00000u;
        v = __uint_as_float(u);
    } else {
        v = (a < 0.25f) ? 0.0f : ((a < 0.75f) ? 0.5f : 1.0f);
    }
    return copysignf(v, x);
}

__device__ __forceinline__ float fp8_e4m3_round(float s) {
    __nv_fp8_storage_t st = __nv_cvt_float_to_fp8(s, __NV_SATFINITE, __NV_E4M3);
    return __half2float(__nv_cvt_fp8_to_halfraw(st, __NV_E4M3));
}

// Quantize one 16-element block -> dequantized bf16 (exact: <=6 sig bits)
__device__ __forceinline__ void quant16(const float y[16], float gs, unsigned short o[16]) {
    float amax = 0.0f;
#pragma unroll
    for (int j = 0; j < 16; j++) amax = fmaxf(amax, fabsf(y[j]));
    float sc = fminf((amax / 6.0f) * gs, 448.0f);
    sc = fp8_e4m3_round(sc);
    float safe = (sc > 0.0f) ? sc : 1.0f;
    float mult = gs / safe;
#pragma unroll
    for (int j = 0; j < 16; j++) {
        float q = fp4_round_dev(y[j] * mult);
        o[j] = __bfloat16_as_ushort(__float2bfloat16(q * sc));
    }
}

// ----------------------------------------------------------------------------
// Weight quantize-dequantize: w rows [row0, ...) -> bf16
// ----------------------------------------------------------------------------
__global__ void __launch_bounds__(256) quantw_kernel(const float* __restrict__ w,
                                                     const float* __restrict__ wg,
                                                     __nv_bfloat16* __restrict__ bout,
                                                     int row0) {
    const int r = blockIdx.x + row0;     // global row 0 .. 3*HD-1
    const int tid = threadIdx.x;
    const float gs = wg[r >> 12];
    const float* rp = w + (size_t)r * HD + tid * 16;
    float y[16];
#pragma unroll
    for (int k = 0; k < 4; k++) {
        float4 x = *(const float4*)(rp + k * 4);
        y[k*4+0] = x.x; y[k*4+1] = x.y; y[k*4+2] = x.z; y[k*4+3] = x.w;
    }
    unsigned short o16[16];
    quant16(y, gs, o16);
    uint32_t pk[8];
#pragma unroll
    for (int k = 0; k < 8; k++) pk[k] = (uint32_t)o16[2*k] | ((uint32_t)o16[2*k+1] << 16);
    uint4* dst = (uint4*)(bout + (size_t)r * HD + tid * 16);
    dst[0] = make_uint4(pk[0], pk[1], pk[2], pk[3]);
    dst[1] = make_uint4(pk[4], pk[5], pk[6], pk[7]);
}

// ----------------------------------------------------------------------------
// Fused (optional relu) + rmsnorm + (quantize to bf16 A  |  fp32 y out)
// ----------------------------------------------------------------------------
__global__ void __launch_bounds__(256) norm_quant_kernel(
    const float* __restrict__ in, float* __restrict__ resid_out,
    const float* __restrict__ nw, const float* __restrict__ gsp,
    __nv_bfloat16* __restrict__ aout, float* __restrict__ yout, int do_relu) {
    __shared__ float red[8];
    __shared__ float s_r;
    const int t = blockIdx.x;
    const int tid = threadIdx.x;
    const int wid = tid >> 5, lid = tid & 31;

    const float* rowp = in + (size_t)t * HD + tid * 16;
    float v[16];
#pragma unroll
    for (int k = 0; k < 4; k++) {
        float4 x = *(const float4*)(rowp + k * 4);
        v[k*4+0] = x.x; v[k*4+1] = x.y; v[k*4+2] = x.z; v[k*4+3] = x.w;
    }
    if (do_relu) {
#pragma unroll
        for (int j = 0; j < 16; j++) v[j] = fmaxf(v[j], 0.0f);
        float* rp = resid_out + (size_t)t * HD + tid * 16;
#pragma unroll
        for (int k = 0; k < 4; k++)
            *(float4*)(rp + k * 4) = make_float4(v[k*4+0], v[k*4+1], v[k*4+2], v[k*4+3]);
    }
    float ss = 0.0f;
#pragma unroll
    for (int j = 0; j < 16; j++) ss += v[j] * v[j];
#pragma unroll
    for (int o = 16; o > 0; o >>= 1) ss += __shfl_xor_sync(0xffffffffu, ss, o);
    if (lid == 0) red[wid] = ss;
    __syncthreads();
    if (tid == 0) {
        float s = red[0]+red[1]+red[2]+red[3]+red[4]+red[5]+red[6]+red[7];
        s_r = rsqrtf(s * (1.0f / (float)HD) + 1e-6f);
    }
    __syncthreads();
    const float r = s_r;

    const float* wp = nw + tid * 16;
    float y[16];
#pragma unroll
    for (int k = 0; k < 4; k++) {
        float4 wv = *(const float4*)(wp + k * 4);
        y[k*4+0] = (v[k*4+0] * r) * wv.x;
        y[k*4+1] = (v[k*4+1] * r) * wv.y;
        y[k*4+2] = (v[k*4+2] * r) * wv.z;
        y[k*4+3] = (v[k*4+3] * r) * wv.w;
    }
    if (yout) {
        float* op = yout + (size_t)t * HD + tid * 16;
#pragma unroll
        for (int k = 0; k < 4; k++)
            *(float4*)(op + k * 4) = make_float4(y[k*4+0], y[k*4+1], y[k*4+2], y[k*4+3]);
    } else {
        unsigned short o16[16];
        quant16(y, gsp[0], o16);
        uint32_t pk[8];
#pragma unroll
        for (int k = 0; k < 8; k++) pk[k] = (uint32_t)o16[2*k] | ((uint32_t)o16[2*k+1] << 16);
        uint4* dst = (uint4*)(aout + (size_t)t * HD + tid * 16);
        dst[0] = make_uint4(pk[0], pk[1], pk[2], pk[3]);
        dst[1] = make_uint4(pk[4], pk[5], pk[6], pk[7]);
    }
}

// ----------------------------------------------------------------------------
// HMMA GEMM: resid[m,n] += (sum_k A[m,k]*B[n,k]) * alpha
// CTA tile 128x128, BK=64, SW128 smem, 3-stage cp.async pipeline, 96 KB smem
// -> 2 CTAs resident per SM (occupancy fix: hide barrier/LDSM bubbles).
// 256 threads = 8 warps in a 2(M) x 4(N) grid; warp tile 64x32.
// ----------------------------------------------------------------------------
#define BM 128
#define BN 128
#define BK 64
#define A_BYTES  (BM * 128)              // 16 KB per stage
#define B_BYTES  (BN * 128)              // 16 KB per stage
#define STAGE_BYTES (A_BYTES + B_BYTES)  // 32 KB
#define NSTAGE 3
#define GEMM_SMEM (NSTAGE * STAGE_BYTES) // 96 KB

__device__ __forceinline__ uint32_t sw128(uint32_t off) {
    return off ^ ((off >> 3) & 0x70u);
}

__device__ __forceinline__ void cp16(uint32_t saddr, const void* gaddr) {
    asm volatile("cp.async.cg.shared.global [%0], [%1], 16;" :: "r"(saddr), "l"(gaddr));
}

__device__ __forceinline__ void ldm_x4(uint32_t* r, uint32_t addr) {
    asm volatile("ldmatrix.sync.aligned.m8n8.x4.shared.b16 {%0,%1,%2,%3}, [%4];"
                 : "=r"(r[0]), "=r"(r[1]), "=r"(r[2]), "=r"(r[3]) : "r"(addr));
}

__device__ __forceinline__ void mma16816(float* c, const uint32_t* a, const uint32_t* b) {
    asm volatile(
        "mma.sync.aligned.m16n8k16.row.col.f32.bf16.bf16.f32 "
        "{%0,%1,%2,%3}, {%4,%5,%6,%7}, {%8,%9}, {%0,%1,%2,%3};"
        : "+f"(c[0]), "+f"(c[1]), "+f"(c[2]), "+f"(c[3])
        : "r"(a[0]), "r"(a[1]), "r"(a[2]), "r"(a[3]), "r"(b[0]), "r"(b[1]));
}

__global__ void __launch_bounds__(256, 2) gemm_kernel(
    const __nv_bfloat16* __restrict__ A, const __nv_bfloat16* __restrict__ B,
    const float* __restrict__ agp, const float* __restrict__ wgp,
    float* __restrict__ resid) {
    extern __shared__ char smem[];
    const uint32_t sb = (uint32_t)__cvta_generic_to_shared(smem);
    const int tid = threadIdx.x;
    const int wid = tid >> 5, lane = tid & 31;
    const int n0 = blockIdx.x * BN, m0 = blockIdx.y * BM;
    const int wm = (wid & 1) * 64;       // warp M offset (2 warps cover 128)
    const int wn = (wid >> 1) * 32;      // warp N offset (4 warps cover 128)

    const __nv_bfloat16* Ab = A + (size_t)m0 * HD;
    const __nv_bfloat16* Bb = B + (size_t)n0 * HD;

    // per-warp swizzled LDSM base addresses (ks = 0); ks advances by XOR ks*32
    uint32_t aOff[4], bOff[2];
#pragma unroll
    for (int mt = 0; mt < 4; mt++) {
        int row = wm + mt * 16 + (lane & 15);
        aOff[mt] = sw128((uint32_t)(row * 128 + ((lane >> 4) << 4)));
    }
#pragma unroll
    for (int p = 0; p < 2; p++) {
        int nrow = wn + p * 16 + ((lane >> 4) << 3) + (lane & 7);
        bOff[p] = sw128((uint32_t)(nrow * 128 + (((lane >> 3) & 1) << 4)));
    }

    float acc[4][4][4];
#pragma unroll
    for (int i = 0; i < 4; i++)
#pragma unroll
        for (int j = 0; j < 4; j++)
#pragma unroll
            for (int q = 0; q < 4; q++) acc[i][j][q] = 0.0f;

    // --- async stage loader: A 1024 + B 1024 x 16B chunks, 256 threads
    auto load_tile = [&](int buf, int c) {
        const int k0 = c * BK;
        const uint32_t abase = sb + (uint32_t)buf * STAGE_BYTES;
        const uint32_t bbase = abase + A_BYTES;
#pragma unroll
        for (int it = 0; it < 4; it++) {
            int l = tid + it * 256;              // 0..1023
            int row = l >> 3, ch = l & 7;
            uint32_t sw = sw128((uint32_t)(row * 128 + ch * 16));
            cp16(abase + sw, Ab + (size_t)row * HD + k0 + ch * 8);
            cp16(bbase + sw, Bb + (size_t)row * HD + k0 + ch * 8);
        }
        asm volatile("cp.async.commit_group;");
    };

    const int NT = HD / BK;                       // 64
    load_tile(0, 0);
    load_tile(1, 1);

    for (int c = 0; c < NT; c++) {
        if (c + 1 < NT) asm volatile("cp.async.wait_group 1;");
        else            asm volatile("cp.async.wait_group 0;");
        __syncthreads();
        if (c + 2 < NT) load_tile((c + 2) % NSTAGE, c + 2);

        const uint32_t aBase = sb + (uint32_t)(c % NSTAGE) * STAGE_BYTES;
        const uint32_t bBase = aBase + A_BYTES;
#pragma unroll
        for (int ks = 0; ks < 4; ks++) {
            const uint32_t kx = (uint32_t)(ks * 32);
            uint32_t af[4][4];
#pragma unroll
            for (int mt = 0; mt < 4; mt++)
                ldm_x4(af[mt], aBase + (aOff[mt] ^ kx));
            uint32_t bf[2][4];
#pragma unroll
            for (int p = 0; p < 2; p++)
                ldm_x4(bf[p], bBase + (bOff[p] ^ kx));
#pragma unroll
            for (int mt = 0; mt < 4; mt++)
#pragma unroll
                for (int p = 0; p < 2; p++) {
                    mma16816(acc[mt][2 * p],     af[mt], &bf[p][0]);
                    mma16816(acc[mt][2 * p + 1], af[mt], &bf[p][2]);
                }
        }
    }

    // --- epilogue: resid += acc * alpha (fragment-direct float2 RMW)
    const float alpha = 1.0f / (wgp[0] * agp[0]);
#pragma unroll
    for (int mt = 0; mt < 4; mt++) {
        int rbase = m0 + wm + mt * 16 + (lane >> 2);
#pragma unroll
        for (int nt = 0; nt < 4; nt++) {
            int col = n0 + wn + nt * 8 + (lane & 3) * 2;
            {
                float* p = resid + (size_t)rbase * HD + col;
                float2 r = *(float2*)p;
                r.x += acc[mt][nt][0] * alpha;
                r.y += acc[mt][nt][1] * alpha;
                *(float2*)p = r;
            }
            {
                float* p = resid + (size_t)(rbase + 8) * HD + col;
                float2 r = *(float2*)p;
                r.x += acc[mt][nt][2] * alpha;
                r.y += acc[mt][nt][3] * alpha;
                *(float2*)p = r;
            }
        }
    }
}

// ----------------------------------------------------------------------------
// Launch (single stream; quantw split in two so ncu -s 5 lands on a GEMM)
// ----------------------------------------------------------------------------
extern "C" void kernel_launch(void* const* d_in, const int* in_sizes, int n_in,
                              void* d_out, int out_size) {
    (void)in_sizes; (void)n_in; (void)out_size;
    const float* hs = (const float*)d_in[0];
    const float* nw = (const float*)d_in[1];
    const float* w  = (const float*)d_in[2];
    const float* ag = (const float*)d_in[3];
    const float* wg = (const float*)d_in[4];
    float* out = (float*)d_out;

    void *pA = nullptr, *pB = nullptr, *pR = nullptr;
    cudaGetSymbolAddress(&pA, g_Abuf);
    cudaGetSymbolAddress(&pB, g_Bbuf);
    cudaGetSymbolAddress(&pR, g_resid);
    __nv_bfloat16* Abuf = (__nv_bfloat16*)pA;
    __nv_bfloat16* Bbuf = (__nv_bfloat16*)pB;
    float* resid = (float*)pR;

    static bool attr_done = false;
    if (!attr_done) {
        cudaFuncSetAttribute(gemm_kernel, cudaFuncAttributeMaxDynamicSharedMemorySize,
                             GEMM_SMEM);
        attr_done = true;
    }

    // weights -> dequantized bf16 B (2 launches)
    quantw_kernel<<<2 * HD, 256>>>(w, wg, Bbuf, 0);
    quantw_kernel<<<1 * HD, 256>>>(w, wg, Bbuf, 2 * HD);
    // relu + rmsnorm(norm_w[0]) + quant(agscale[0]) ; resid = relu(hs)
    norm_quant_kernel<<<TT, 256>>>(hs, resid, nw, ag, Abuf, nullptr, 1);

    for (int i = 0; i < 3; i++) {
        gemm_kernel<<<dim3(HD / BN, TT / BM), 256, GEMM_SMEM>>>(
            Abuf, Bbuf + (size_t)i * HD * HD, ag + i, wg + i, resid);
        if (i < 2) {
            norm_quant_kernel<<<TT, 256>>>(resid, nullptr, nw + (size_t)(i + 1) * HD,
                                           ag + (i + 1), Abuf, nullptr, 0);
        } else {
            norm_quant_kernel<<<TT, 256>>>(resid, nullptr, nw + 3ull * HD,
                                           nullptr, nullptr, out, 0);
        }
    }
}

// round 13
// speedup vs baseline: 1.0948x; 1.0131x over previous
#include <cuda_runtime.h>
#include <cuda_bf16.h>
#include <cuda_fp8.h>
#include <cstdint>

#define HD 4096
#define TT 8192

// ----------------------------------------------------------------------------
// Scratch (static device globals — no allocation anywhere)
// ----------------------------------------------------------------------------
__device__ float          g_resid[(size_t)TT * HD];          // 128 MB
__device__ __nv_bfloat16  g_Abuf[(size_t)TT * HD];           // 64 MB
__device__ __nv_bfloat16  g_Bbuf[3ull * HD * HD];            // 96 MB

// ----------------------------------------------------------------------------
// FP4 / FP8 emulation matching the reference semantics
// ----------------------------------------------------------------------------
// e2m1 round-to-nearest with ties-up (== jnp.searchsorted(mids, a, 'right')).
__device__ __forceinline__ float fp4_round_dev(float x) {
    float a = fabsf(x);
    float v;
    if (a >= 1.0f) {
        a = fminf(a, 6.0f);
        uint32_t u = __float_as_uint(a);
        u = (u + 0x00200000u) & 0xFFC00000u;
        v = __uint_as_float(u);
    } else {
        v = (a < 0.25f) ? 0.0f : ((a < 0.75f) ? 0.5f : 1.0f);
    }
    return copysignf(v, x);
}

__device__ __forceinline__ float fp8_e4m3_round(float s) {
    __nv_fp8_storage_t st = __nv_cvt_float_to_fp8(s, __NV_SATFINITE, __NV_E4M3);
    return __half2float(__nv_cvt_fp8_to_halfraw(st, __NV_E4M3));
}

// Quantize one 16-element block -> dequantized bf16 (exact: <=6 sig bits)
__device__ __forceinline__ void quant16(const float y[16], float gs, unsigned short o[16]) {
    float amax = 0.0f;
#pragma unroll
    for (int j = 0; j < 16; j++) amax = fmaxf(amax, fabsf(y[j]));
    float sc = fminf((amax / 6.0f) * gs, 448.0f);
    sc = fp8_e4m3_round(sc);
    float safe = (sc > 0.0f) ? sc : 1.0f;
    float mult = gs / safe;
#pragma unroll
    for (int j = 0; j < 16; j++) {
        float q = fp4_round_dev(y[j] * mult);
        o[j] = __bfloat16_as_ushort(__float2bfloat16(q * sc));
    }
}

// ----------------------------------------------------------------------------
// Weight quantize-dequantize: w rows [row0, ...) -> bf16
// ----------------------------------------------------------------------------
__global__ void __launch_bounds__(256) quantw_kernel(const float* __restrict__ w,
                                                     const float* __restrict__ wg,
                                                     __nv_bfloat16* __restrict__ bout,
                                                     int row0) {
    const int r = blockIdx.x + row0;     // global row 0 .. 3*HD-1
    const int tid = threadIdx.x;
    const float gs = wg[r >> 12];
    const float* rp = w + (size_t)r * HD + tid * 16;
    float y[16];
#pragma unroll
    for (int k = 0; k < 4; k++) {
        float4 x = *(const float4*)(rp + k * 4);
        y[k*4+0] = x.x; y[k*4+1] = x.y; y[k*4+2] = x.z; y[k*4+3] = x.w;
    }
    unsigned short o16[16];
    quant16(y, gs, o16);
    uint32_t pk[8];
#pragma unroll
    for (int k = 0; k < 8; k++) pk[k] = (uint32_t)o16[2*k] | ((uint32_t)o16[2*k+1] << 16);
    uint4* dst = (uint4*)(bout + (size_t)r * HD + tid * 16);
    dst[0] = make_uint4(pk[0], pk[1], pk[2], pk[3]);
    dst[1] = make_uint4(pk[4], pk[5], pk[6], pk[7]);
}

// ----------------------------------------------------------------------------
// Fused (optional relu) + rmsnorm + (quantize to bf16 A  |  fp32 y out)
// single __syncthreads: all threads redundantly reduce the 8 warp partials
// ----------------------------------------------------------------------------
__global__ void __launch_bounds__(256) norm_quant_kernel(
    const float* __restrict__ in, float* __restrict__ resid_out,
    const float* __restrict__ nw, const float* __restrict__ gsp,
    __nv_bfloat16* __restrict__ aout, float* __restrict__ yout, int do_relu) {
    __shared__ float red[8];
    const int t = blockIdx.x;
    const int tid = threadIdx.x;
    const int wid = tid >> 5, lid = tid & 31;

    const float* rowp = in + (size_t)t * HD + tid * 16;
    float v[16];
#pragma unroll
    for (int k = 0; k < 4; k++) {
        float4 x = *(const float4*)(rowp + k * 4);
        v[k*4+0] = x.x; v[k*4+1] = x.y; v[k*4+2] = x.z; v[k*4+3] = x.w;
    }
    if (do_relu) {
#pragma unroll
        for (int j = 0; j < 16; j++) v[j] = fmaxf(v[j], 0.0f);
        float* rp = resid_out + (size_t)t * HD + tid * 16;
#pragma unroll
        for (int k = 0; k < 4; k++)
            *(float4*)(rp + k * 4) = make_float4(v[k*4+0], v[k*4+1], v[k*4+2], v[k*4+3]);
    }
    float ss = 0.0f;
#pragma unroll
    for (int j = 0; j < 16; j++) ss += v[j] * v[j];
#pragma unroll
    for (int o = 16; o > 0; o >>= 1) ss += __shfl_xor_sync(0xffffffffu, ss, o);
    if (lid == 0) red[wid] = ss;
    __syncthreads();
    float s = red[0]+red[1]+red[2]+red[3]+red[4]+red[5]+red[6]+red[7];
    const float r = rsqrtf(s * (1.0f / (float)HD) + 1e-6f);

    const float* wp = nw + tid * 16;
    float y[16];
#pragma unroll
    for (int k = 0; k < 4; k++) {
        float4 wv = *(const float4*)(wp + k * 4);
        y[k*4+0] = (v[k*4+0] * r) * wv.x;
        y[k*4+1] = (v[k*4+1] * r) * wv.y;
        y[k*4+2] = (v[k*4+2] * r) * wv.z;
        y[k*4+3] = (v[k*4+3] * r) * wv.w;
    }
    if (yout) {
        float* op = yout + (size_t)t * HD + tid * 16;
#pragma unroll
        for (int k = 0; k < 4; k++)
            *(float4*)(op + k * 4) = make_float4(y[k*4+0], y[k*4+1], y[k*4+2], y[k*4+3]);
    } else {
        unsigned short o16[16];
        quant16(y, gsp[0], o16);
        uint32_t pk[8];
#pragma unroll
        for (int k = 0; k < 8; k++) pk[k] = (uint32_t)o16[2*k] | ((uint32_t)o16[2*k+1] << 16);
        uint4* dst = (uint4*)(aout + (size_t)t * HD + tid * 16);
        dst[0] = make_uint4(pk[0], pk[1], pk[2], pk[3]);
        dst[1] = make_uint4(pk[4], pk[5], pk[6], pk[7]);
    }
}

// ----------------------------------------------------------------------------
// HMMA GEMM: resid[m,n] += (sum_k A[m,k]*B[n,k]) * alpha
// CTA tile 128x128, BK=64, SW128 smem, 3-stage cp.async, 96 KB -> 2 CTAs/SM.
// 256 threads = 8 warps in a 2(M) x 4(N) grid; warp tile 64x32.
// ks order staggered per warp parity; af loads interleaved with their MMAs.
// ----------------------------------------------------------------------------
#define BM 128
#define BN 128
#define BK 64
#define A_BYTES  (BM * 128)              // 16 KB per stage
#define B_BYTES  (BN * 128)              // 16 KB per stage
#define STAGE_BYTES (A_BYTES + B_BYTES)  // 32 KB
#define NSTAGE 3
#define GEMM_SMEM (NSTAGE * STAGE_BYTES) // 96 KB

__device__ __forceinline__ uint32_t sw128(uint32_t off) {
    return off ^ ((off >> 3) & 0x70u);
}

__device__ __forceinline__ void cp16(uint32_t saddr, const void* gaddr) {
    asm volatile("cp.async.cg.shared.global [%0], [%1], 16;" :: "r"(saddr), "l"(gaddr));
}

__device__ __forceinline__ void ldm_x4(uint32_t* r, uint32_t addr) {
    asm volatile("ldmatrix.sync.aligned.m8n8.x4.shared.b16 {%0,%1,%2,%3}, [%4];"
                 : "=r"(r[0]), "=r"(r[1]), "=r"(r[2]), "=r"(r[3]) : "r"(addr));
}

__device__ __forceinline__ void mma16816(float* c, const uint32_t* a, const uint32_t* b) {
    asm volatile(
        "mma.sync.aligned.m16n8k16.row.col.f32.bf16.bf16.f32 "
        "{%0,%1,%2,%3}, {%4,%5,%6,%7}, {%8,%9}, {%0,%1,%2,%3};"
        : "+f"(c[0]), "+f"(c[1]), "+f"(c[2]), "+f"(c[3])
        : "r"(a[0]), "r"(a[1]), "r"(a[2]), "r"(a[3]), "r"(b[0]), "r"(b[1]));
}

__global__ void __launch_bounds__(256, 2) gemm_kernel(
    const __nv_bfloat16* __restrict__ A, const __nv_bfloat16* __restrict__ B,
    const float* __restrict__ agp, const float* __restrict__ wgp,
    float* __restrict__ resid) {
    extern __shared__ char smem[];
    const uint32_t sb = (uint32_t)__cvta_generic_to_shared(smem);
    const int tid = threadIdx.x;
    const int wid = tid >> 5, lane = tid & 31;
    const int n0 = blockIdx.x * BN, m0 = blockIdx.y * BM;
    const int wm = (wid & 1) * 64;       // warp M offset (2 warps cover 128)
    const int wn = (wid >> 1) * 32;      // warp N offset (4 warps cover 128)
    const uint32_t kstag = (uint32_t)((wid & 1) << 1); // stagger ks per warp parity

    const __nv_bfloat16* Ab = A + (size_t)m0 * HD;
    const __nv_bfloat16* Bb = B + (size_t)n0 * HD;

    // per-warp swizzled LDSM base addresses (ks = 0); ks advances by XOR ks*32
    uint32_t aOff[4], bOff[2];
#pragma unroll
    for (int mt = 0; mt < 4; mt++) {
        int row = wm + mt * 16 + (lane & 15);
        aOff[mt] = sw128((uint32_t)(row * 128 + ((lane >> 4) << 4)));
    }
#pragma unroll
    for (int p = 0; p < 2; p++) {
        int nrow = wn + p * 16 + ((lane >> 4) << 3) + (lane & 7);
        bOff[p] = sw128((uint32_t)(nrow * 128 + (((lane >> 3) & 1) << 4)));
    }

    float acc[4][4][4];
#pragma unroll
    for (int i = 0; i < 4; i++)
#pragma unroll
        for (int j = 0; j < 4; j++)
#pragma unroll
            for (int q = 0; q < 4; q++) acc[i][j][q] = 0.0f;

    // --- async stage loader: A 1024 + B 1024 x 16B chunks, 256 threads
    auto load_tile = [&](int buf, int c) {
        const int k0 = c * BK;
        const uint32_t abase = sb + (uint32_t)buf * STAGE_BYTES;
        const uint32_t bbase = abase + A_BYTES;
#pragma unroll
        for (int it = 0; it < 4; it++) {
            int l = tid + it * 256;              // 0..1023
            int row = l >> 3, ch = l & 7;
            uint32_t sw = sw128((uint32_t)(row * 128 + ch * 16));
            cp16(abase + sw, Ab + (size_t)row * HD + k0 + ch * 8);
            cp16(bbase + sw, Bb + (size_t)row * HD + k0 + ch * 8);
        }
        asm volatile("cp.async.commit_group;");
    };

    const int NT = HD / BK;                       // 64
    load_tile(0, 0);
    load_tile(1, 1);

    for (int c = 0; c < NT; c++) {
        if (c + 1 < NT) asm volatile("cp.async.wait_group 1;");
        else            asm volatile("cp.async.wait_group 0;");
        __syncthreads();
        if (c + 2 < NT) load_tile((c + 2) % NSTAGE, c + 2);

        const uint32_t aBase = sb + (uint32_t)(c % NSTAGE) * STAGE_BYTES;
        const uint32_t bBase = aBase + A_BYTES;
#pragma unroll
        for (int ks0 = 0; ks0 < 4; ks0++) {
            // per-warp-parity staggered ks order: 0,1,2,3 vs 2,3,0,1
            const uint32_t kx = (((uint32_t)ks0 ^ kstag) & 3u) * 32u;
            // B fragments first (8 regs), then per-mt: load af, use immediately
            uint32_t bf[2][4];
#pragma unroll
            for (int p = 0; p < 2; p++)
                ldm_x4(bf[p], bBase + (bOff[p] ^ kx));
#pragma unroll
            for (int mt = 0; mt < 4; mt++) {
                uint32_t af[4];
                ldm_x4(af, aBase + (aOff[mt] ^ kx));
#pragma unroll
                for (int p = 0; p < 2; p++) {
                    mma16816(acc[mt][2 * p],     af, &bf[p][0]);
                    mma16816(acc[mt][2 * p + 1], af, &bf[p][2]);
                }
            }
        }
    }

    // --- epilogue: resid += acc * alpha (fragment-direct float2 RMW)
    const float alpha = 1.0f / (wgp[0] * agp[0]);
#pragma unroll
    for (int mt = 0; mt < 4; mt++) {
        int rbase = m0 + wm + mt * 16 + (lane >> 2);
#pragma unroll
        for (int nt = 0; nt < 4; nt++) {
            int col = n0 + wn + nt * 8 + (lane & 3) * 2;
            {
                float* p = resid + (size_t)rbase * HD + col;
                float2 r = *(float2*)p;
                r.x += acc[mt][nt][0] * alpha;
                r.y += acc[mt][nt][1] * alpha;
                *(float2*)p = r;
            }
            {
                float* p = resid + (size_t)(rbase + 8) * HD + col;
                float2 r = *(float2*)p;
                r.x += acc[mt][nt][2] * alpha;
                r.y += acc[mt][nt][3] * alpha;
                *(float2*)p = r;
            }
        }
    }
}

// ----------------------------------------------------------------------------
// Launch (single stream; quantw split in two so ncu -s 5 lands on a GEMM)
// ----------------------------------------------------------------------------
extern "C" void kernel_launch(void* const* d_in, const int* in_sizes, int n_in,
                              void* d_out, int out_size) {
    (void)in_sizes; (void)n_in; (void)out_size;
    const float* hs = (const float*)d_in[0];
    const float* nw = (const float*)d_in[1];
    const float* w  = (const float*)d_in[2];
    const float* ag = (const float*)d_in[3];
    const float* wg = (const float*)d_in[4];
    float* out = (float*)d_out;

    void *pA = nullptr, *pB = nullptr, *pR = nullptr;
    cudaGetSymbolAddress(&pA, g_Abuf);
    cudaGetSymbolAddress(&pB, g_Bbuf);
    cudaGetSymbolAddress(&pR, g_resid);
    __nv_bfloat16* Abuf = (__nv_bfloat16*)pA;
    __nv_bfloat16* Bbuf = (__nv_bfloat16*)pB;
    float* resid = (float*)pR;

    static bool attr_done = false;
    if (!attr_done) {
        cudaFuncSetAttribute(gemm_kernel, cudaFuncAttributeMaxDynamicSharedMemorySize,
                             GEMM_SMEM);
        attr_done = true;
    }

    // weights -> dequantized bf16 B (2 launches)
    quantw_kernel<<<2 * HD, 256>>>(w, wg, Bbuf, 0);
    quantw_kernel<<<1 * HD, 256>>>(w, wg, Bbuf, 2 * HD);
    // relu + rmsnorm(norm_w[0]) + quant(agscale[0]) ; resid = relu(hs)
    norm_quant_kernel<<<TT, 256>>>(hs, resid, nw, ag, Abuf, nullptr, 1);

    for (int i = 0; i < 3; i++) {
        gemm_kernel<<<dim3(HD / BN, TT / BM), 256, GEMM_SMEM>>>(
            Abuf, Bbuf + (size_t)i * HD * HD, ag + i, wg + i, resid);
        if (i < 2) {
            norm_quant_kernel<<<TT, 256>>>(resid, nullptr, nw + (size_t)(i + 1) * HD,
                                           ag + (i + 1), Abuf, nullptr, 0);
        } else {
            norm_quant_kernel<<<TT, 256>>>(resid, nullptr, nw + 3ull * HD,
                                           nullptr, nullptr, out, 0);
        }
    }
}

// round 14
// speedup vs baseline: 1.1166x; 1.0199x over previous
#include <cuda_runtime.h>
#include <cuda_bf16.h>
#include <cuda_fp8.h>
#include <cstdint>

#define HD 4096
#define TT 8192

// ----------------------------------------------------------------------------
// Scratch (static device globals — no allocation anywhere)
// ----------------------------------------------------------------------------
__device__ float          g_resid[(size_t)TT * HD];          // 128 MB
__device__ __nv_bfloat16  g_Abuf[(size_t)TT * HD];           // 64 MB
__device__ __nv_bfloat16  g_Bbuf[3ull * HD * HD];            // 96 MB

// ----------------------------------------------------------------------------
// FP4 / FP8 emulation matching the reference semantics
// ----------------------------------------------------------------------------
// e2m1 round-to-nearest with ties-up (== jnp.searchsorted(mids, a, 'right')).
__device__ __forceinline__ float fp4_round_dev(float x) {
    float a = fabsf(x);
    float v;
    if (a >= 1.0f) {
        a = fminf(a, 6.0f);
        uint32_t u = __float_as_uint(a);
        u = (u + 0x00200000u) & 0xFFC00000u;
        v = __uint_as_float(u);
    } else {
        v = (a < 0.25f) ? 0.0f : ((a < 0.75f) ? 0.5f : 1.0f);
    }
    return copysignf(v, x);
}

__device__ __forceinline__ float fp8_e4m3_round(float s) {
    __nv_fp8_storage_t st = __nv_cvt_float_to_fp8(s, __NV_SATFINITE, __NV_E4M3);
    return __half2float(__nv_cvt_fp8_to_halfraw(st, __NV_E4M3));
}

// Quantize 8 elements (half of a 16-block; amax16 combined via shfl pair).
// Returns packed bf16x2 words of q*sc (exact in bf16: <=6 sig bits).
__device__ __forceinline__ void quant8_pair(const float y[8], float gs,
                                            uint32_t pk[4]) {
    float amax = 0.0f;
#pragma unroll
    for (int j = 0; j < 8; j++) amax = fmaxf(amax, fabsf(y[j]));
    amax = fmaxf(amax, __shfl_xor_sync(0xffffffffu, amax, 1));
    float sc = fminf((amax / 6.0f) * gs, 448.0f);
    sc = fp8_e4m3_round(sc);
    float safe = (sc > 0.0f) ? sc : 1.0f;
    float mult = gs / safe;
    unsigned short o[8];
#pragma unroll
    for (int j = 0; j < 8; j++) {
        float q = fp4_round_dev(y[j] * mult);
        o[j] = __bfloat16_as_ushort(__float2bfloat16(q * sc));
    }
#pragma unroll
    for (int k = 0; k < 4; k++) pk[k] = (uint32_t)o[2*k] | ((uint32_t)o[2*k+1] << 16);
}

// ----------------------------------------------------------------------------
// Weight quantize-dequantize: w rows [row0, ...) -> bf16 (512 thr, 8 elem/thr)
// ----------------------------------------------------------------------------
__global__ void __launch_bounds__(512) quantw_kernel(const float* __restrict__ w,
                                                     const float* __restrict__ wg,
                                                     __nv_bfloat16* __restrict__ bout,
                                                     int row0) {
    const int r = blockIdx.x + row0;     // global row 0 .. 3*HD-1
    const int tid = threadIdx.x;
    const float gs = wg[r >> 12];
    const float* rp = w + (size_t)r * HD + tid * 8;
    float y[8];
#pragma unroll
    for (int k = 0; k < 2; k++) {
        float4 x = *(const float4*)(rp + k * 4);
        y[k*4+0] = x.x; y[k*4+1] = x.y; y[k*4+2] = x.z; y[k*4+3] = x.w;
    }
    uint32_t pk[4];
    quant8_pair(y, gs, pk);
    *(uint4*)(bout + (size_t)r * HD + tid * 8) = make_uint4(pk[0], pk[1], pk[2], pk[3]);
}

// ----------------------------------------------------------------------------
// Fused (optional relu) + rmsnorm + (quantize to bf16 A  |  fp32 y out)
// 512 threads, 8 elems/thread, single __syncthreads
// ----------------------------------------------------------------------------
__global__ void __launch_bounds__(512) norm_quant_kernel(
    const float* __restrict__ in, float* __restrict__ resid_out,
    const float* __restrict__ nw, const float* __restrict__ gsp,
    __nv_bfloat16* __restrict__ aout, float* __restrict__ yout, int do_relu) {
    __shared__ float red[16];
    const int t = blockIdx.x;
    const int tid = threadIdx.x;
    const int wid = tid >> 5, lid = tid & 31;

    const float* rowp = in + (size_t)t * HD + tid * 8;
    float v[8];
#pragma unroll
    for (int k = 0; k < 2; k++) {
        float4 x = *(const float4*)(rowp + k * 4);
        v[k*4+0] = x.x; v[k*4+1] = x.y; v[k*4+2] = x.z; v[k*4+3] = x.w;
    }
    if (do_relu) {
#pragma unroll
        for (int j = 0; j < 8; j++) v[j] = fmaxf(v[j], 0.0f);
        float* rp = resid_out + (size_t)t * HD + tid * 8;
#pragma unroll
        for (int k = 0; k < 2; k++)
            *(float4*)(rp + k * 4) = make_float4(v[k*4+0], v[k*4+1], v[k*4+2], v[k*4+3]);
    }
    float ss = 0.0f;
#pragma unroll
    for (int j = 0; j < 8; j++) ss += v[j] * v[j];
#pragma unroll
    for (int o = 16; o > 0; o >>= 1) ss += __shfl_xor_sync(0xffffffffu, ss, o);
    if (lid == 0) red[wid] = ss;
    __syncthreads();
    float s = 0.0f;
#pragma unroll
    for (int j = 0; j < 16; j++) s += red[j];
    const float r = rsqrtf(s * (1.0f / (float)HD) + 1e-6f);

    const float* wp = nw + tid * 8;
    float y[8];
#pragma unroll
    for (int k = 0; k < 2; k++) {
        float4 wv = *(const float4*)(wp + k * 4);
        y[k*4+0] = (v[k*4+0] * r) * wv.x;
        y[k*4+1] = (v[k*4+1] * r) * wv.y;
        y[k*4+2] = (v[k*4+2] * r) * wv.z;
        y[k*4+3] = (v[k*4+3] * r) * wv.w;
    }
    if (yout) {
        float* op = yout + (size_t)t * HD + tid * 8;
#pragma unroll
        for (int k = 0; k < 2; k++)
            *(float4*)(op + k * 4) = make_float4(y[k*4+0], y[k*4+1], y[k*4+2], y[k*4+3]);
    } else {
        uint32_t pk[4];
        quant8_pair(y, gsp[0], pk);
        *(uint4*)(aout + (size_t)t * HD + tid * 8) = make_uint4(pk[0], pk[1], pk[2], pk[3]);
    }
}

// ----------------------------------------------------------------------------
// HMMA GEMM: resid[m,n] += (sum_k A[m,k]*B[n,k]) * alpha
// CTA tile 128x128, BK=64, SW128 smem, 3-stage cp.async, 96 KB -> 2 CTAs/SM.
// 256 threads = 8 warps in a 2(M) x 4(N) grid; warp tile 64x32.
// A fragments register-double-buffered (prefetch mt+1 / next-ks mt0).
// ----------------------------------------------------------------------------
#define BM 128
#define BN 128
#define BK 64
#define A_BYTES  (BM * 128)              // 16 KB per stage
#define B_BYTES  (BN * 128)              // 16 KB per stage
#define STAGE_BYTES (A_BYTES + B_BYTES)  // 32 KB
#define NSTAGE 3
#define GEMM_SMEM (NSTAGE * STAGE_BYTES) // 96 KB

__device__ __forceinline__ uint32_t sw128(uint32_t off) {
    return off ^ ((off >> 3) & 0x70u);
}

__device__ __forceinline__ void cp16(uint32_t saddr, const void* gaddr) {
    asm volatile("cp.async.cg.shared.global [%0], [%1], 16;" :: "r"(saddr), "l"(gaddr));
}

__device__ __forceinline__ void ldm_x4(uint32_t* r, uint32_t addr) {
    asm volatile("ldmatrix.sync.aligned.m8n8.x4.shared.b16 {%0,%1,%2,%3}, [%4];"
                 : "=r"(r[0]), "=r"(r[1]), "=r"(r[2]), "=r"(r[3]) : "r"(addr));
}

__device__ __forceinline__ void mma16816(float* c, const uint32_t* a, const uint32_t* b) {
    asm volatile(
        "mma.sync.aligned.m16n8k16.row.col.f32.bf16.bf16.f32 "
        "{%0,%1,%2,%3}, {%4,%5,%6,%7}, {%8,%9}, {%0,%1,%2,%3};"
        : "+f"(c[0]), "+f"(c[1]), "+f"(c[2]), "+f"(c[3])
        : "r"(a[0]), "r"(a[1]), "r"(a[2]), "r"(a[3]), "r"(b[0]), "r"(b[1]));
}

__global__ void __launch_bounds__(256, 2) gemm_kernel(
    const __nv_bfloat16* __restrict__ A, const __nv_bfloat16* __restrict__ B,
    const float* __restrict__ agp, const float* __restrict__ wgp,
    float* __restrict__ resid) {
    extern __shared__ char smem[];
    const uint32_t sb = (uint32_t)__cvta_generic_to_shared(smem);
    const int tid = threadIdx.x;
    const int wid = tid >> 5, lane = tid & 31;
    const int n0 = blockIdx.x * BN, m0 = blockIdx.y * BM;
    const int wm = (wid & 1) * 64;       // warp M offset (2 warps cover 128)
    const int wn = (wid >> 1) * 32;      // warp N offset (4 warps cover 128)
    const uint32_t kstag = (uint32_t)((wid & 1) << 1); // stagger ks per warp parity

    const __nv_bfloat16* Ab = A + (size_t)m0 * HD;
    const __nv_bfloat16* Bb = B + (size_t)n0 * HD;

    // per-warp swizzled LDSM base addresses (ks = 0); ks advances by XOR ks*32
    uint32_t aOff[4], bOff[2];
#pragma unroll
    for (int mt = 0; mt < 4; mt++) {
        int row = wm + mt * 16 + (lane & 15);
        aOff[mt] = sw128((uint32_t)(row * 128 + ((lane >> 4) << 4)));
    }
#pragma unroll
    for (int p = 0; p < 2; p++) {
        int nrow = wn + p * 16 + ((lane >> 4) << 3) + (lane & 7);
        bOff[p] = sw128((uint32_t)(nrow * 128 + (((lane >> 3) & 1) << 4)));
    }

    float acc[4][4][4];
#pragma unroll
    for (int i = 0; i < 4; i++)
#pragma unroll
        for (int j = 0; j < 4; j++)
#pragma unroll
            for (int q = 0; q < 4; q++) acc[i][j][q] = 0.0f;

    // --- async stage loader: A 1024 + B 1024 x 16B chunks, 256 threads
    auto load_tile = [&](int buf, int c) {
        const int k0 = c * BK;
        const uint32_t abase = sb + (uint32_t)buf * STAGE_BYTES;
        const uint32_t bbase = abase + A_BYTES;
#pragma unroll
        for (int it = 0; it < 4; it++) {
            int l = tid + it * 256;              // 0..1023
            int row = l >> 3, ch = l & 7;
            uint32_t sw = sw128((uint32_t)(row * 128 + ch * 16));
            cp16(abase + sw, Ab + (size_t)row * HD + k0 + ch * 8);
            cp16(bbase + sw, Bb + (size_t)row * HD + k0 + ch * 8);
        }
        asm volatile("cp.async.commit_group;");
    };

    const int NT = HD / BK;                       // 64
    load_tile(0, 0);
    load_tile(1, 1);

    for (int c = 0; c < NT; c++) {
        if (c + 1 < NT) asm volatile("cp.async.wait_group 1;");
        else            asm volatile("cp.async.wait_group 0;");
        __syncthreads();
        if (c + 2 < NT) load_tile((c + 2) % NSTAGE, c + 2);

        const uint32_t aBase = sb + (uint32_t)(c % NSTAGE) * STAGE_BYTES;
        const uint32_t bBase = aBase + A_BYTES;

        uint32_t af[2][4];                        // A fragment double buffer
        {
            const uint32_t kx0 = (kstag & 3u) * 32u;
            ldm_x4(af[0], aBase + (aOff[0] ^ kx0));
        }
#pragma unroll
        for (int ks0 = 0; ks0 < 4; ks0++) {
            // per-warp-parity staggered ks order: 0,1,2,3 vs 2,3,0,1
            const uint32_t kx = (((uint32_t)ks0 ^ kstag) & 3u) * 32u;
            uint32_t bf[2][4];
#pragma unroll
            for (int p = 0; p < 2; p++)
                ldm_x4(bf[p], bBase + (bOff[p] ^ kx));
#pragma unroll
            for (int mt = 0; mt < 4; mt++) {
                const int cur = (ks0 * 4 + mt) & 1;
                // prefetch next A fragment (mt+1, or next ks's mt0)
                if (mt < 3) {
                    ldm_x4(af[cur ^ 1], aBase + (aOff[mt + 1] ^ kx));
                } else if (ks0 < 3) {
                    const uint32_t kxn = (((uint32_t)(ks0 + 1) ^ kstag) & 3u) * 32u;
                    ldm_x4(af[cur ^ 1], aBase + (aOff[0] ^ kxn));
                }
#pragma unroll
                for (int p = 0; p < 2; p++) {
                    mma16816(acc[mt][2 * p],     af[cur], &bf[p][0]);
                    mma16816(acc[mt][2 * p + 1], af[cur], &bf[p][2]);
                }
            }
        }
    }

    // --- epilogue: resid += acc * alpha (fragment-direct float2 RMW)
    const float alpha = 1.0f / (wgp[0] * agp[0]);
#pragma unroll
    for (int mt = 0; mt < 4; mt++) {
        int rbase = m0 + wm + mt * 16 + (lane >> 2);
#pragma unroll
        for (int nt = 0; nt < 4; nt++) {
            int col = n0 + wn + nt * 8 + (lane & 3) * 2;
            {
                float* p = resid + (size_t)rbase * HD + col;
                float2 r = *(float2*)p;
                r.x += acc[mt][nt][0] * alpha;
                r.y += acc[mt][nt][1] * alpha;
                *(float2*)p = r;
            }
            {
                float* p = resid + (size_t)(rbase + 8) * HD + col;
                float2 r = *(float2*)p;
                r.x += acc[mt][nt][2] * alpha;
                r.y += acc[mt][nt][3] * alpha;
                *(float2*)p = r;
            }
        }
    }
}

// ----------------------------------------------------------------------------
// Launch (single stream; quantw split in two so ncu -s 5 lands on a GEMM)
// ----------------------------------------------------------------------------
extern "C" void kernel_launch(void* const* d_in, const int* in_sizes, int n_in,
                              void* d_out, int out_size) {
    (void)in_sizes; (void)n_in; (void)out_size;
    const float* hs = (const float*)d_in[0];
    const float* nw = (const float*)d_in[1];
    const float* w  = (const float*)d_in[2];
    const float* ag = (const float*)d_in[3];
    const float* wg = (const float*)d_in[4];
    float* out = (float*)d_out;

    void *pA = nullptr, *pB = nullptr, *pR = nullptr;
    cudaGetSymbolAddress(&pA, g_Abuf);
    cudaGetSymbolAddress(&pB, g_Bbuf);
    cudaGetSymbolAddress(&pR, g_resid);
    __nv_bfloat16* Abuf = (__nv_bfloat16*)pA;
    __nv_bfloat16* Bbuf = (__nv_bfloat16*)pB;
    float* resid = (float*)pR;

    static bool attr_done = false;
    if (!attr_done) {
        cudaFuncSetAttribute(gemm_kernel, cudaFuncAttributeMaxDynamicSharedMemorySize,
                             GEMM_SMEM);
        attr_done = true;
    }

    // weights -> dequantized bf16 B (2 launches)
    quantw_kernel<<<2 * HD, 512>>>(w, wg, Bbuf, 0);
    quantw_kernel<<<1 * HD, 512>>>(w, wg, Bbuf, 2 * HD);
    // relu + rmsnorm(norm_w[0]) + quant(agscale[0]) ; resid = relu(hs)
    norm_quant_kernel<<<TT, 512>>>(hs, resid, nw, ag, Abuf, nullptr, 1);

    for (int i = 0; i < 3; i++) {
        gemm_kernel<<<dim3(HD / BN, TT / BM), 256, GEMM_SMEM>>>(
            Abuf, Bbuf + (size_t)i * HD * HD, ag + i, wg + i, resid);
        if (i < 2) {
            norm_quant_kernel<<<TT, 512>>>(resid, nullptr, nw + (size_t)(i + 1) * HD,
                                           ag + (i + 1), Abuf, nullptr, 0);
        } else {
            norm_quant_kernel<<<TT, 512>>>(resid, nullptr, nw + 3ull * HD,
                                           nullptr, nullptr, out, 0);
        }
    }
}